// round 8
// baseline (speedup 1.0000x reference)
#include <cuda_runtime.h>
#include <cuda_fp16.h>
#include <cstdint>
#include <cstddef>

#define K_DIM 4096
#define N_DIM 11008
#define M_DIM 4096
#define QROWS (K_DIM / 8)

#define BM 256
#define BN 128
#define BK 32
#define A_ST (BK + 8)            // 40 halves = 80B stride
#define B_ST (BN + 8)            // 136 halves = 272B stride
#define NSTAGE 3
#define A_TILE_H (BM * A_ST)     // 10240 halves = 20480 B
#define B_TILE_H (BK * B_ST)     // 4352 halves  = 8704 B
#define STAGE_H (A_TILE_H + B_TILE_H)            // halves per stage
#define SMEM_BYTES (NSTAGE * STAGE_H * 2)        // 87552 B

// Scratch (device-code references only; host must never take these addresses
// directly — GB300 ATS silently reads the host shadow as zeros).
__device__ __half g_W[(size_t)K_DIM * N_DIM];    // dequantized W [K, N]
__device__ __half g_X[(size_t)M_DIM * K_DIM];    // x as fp16 [M, K]

// ---------------------------------------------------------------------------
// Kernel 0: x fp32 -> fp16
// ---------------------------------------------------------------------------
__global__ void convert_x_kernel(const float* __restrict__ x, size_t n) {
    size_t i = ((size_t)blockIdx.x * blockDim.x + threadIdx.x) * 4;
    if (i >= n) return;
    float4 v = *reinterpret_cast<const float4*>(x + i);
    *reinterpret_cast<__half2*>(&g_X[i]) = __floats2half2_rn(v.x, v.y);
    *reinterpret_cast<__half2*>(&g_X[i + 2]) = __floats2half2_rn(v.z, v.w);
}

// ---------------------------------------------------------------------------
// Kernel 1: unpack int4 weights -> fp16 W[K, N]
// ---------------------------------------------------------------------------
__global__ void dequant_kernel(const int* __restrict__ qw,
                               const int* __restrict__ qz,
                               const float* __restrict__ sc) {
    int c = blockIdx.x * blockDim.x + threadIdx.x;
    if (c >= N_DIM) return;
    int kk = blockIdx.y;                       // 0..511 packed K rows
    int packed = qw[kk * N_DIM + c];
    int g = kk >> 4;
    int z = (qz[g * (N_DIM / 8) + (c >> 3)] >> ((c & 7) * 4)) & 15;
    float s = sc[g * N_DIM + c];
    size_t base = (size_t)kk * 8 * N_DIM + c;
#pragma unroll
    for (int i = 0; i < 8; i++) {
        int q = (packed >> (i * 4)) & 15;
        g_W[base + (size_t)i * N_DIM] = __float2half((float)(q - z) * s);
    }
}

// ---------------------------------------------------------------------------
// Kernel 2: fp16 GEMM, 256x128x32 CTA tile, 8 warps of 64x64, 3-stage cp.async.
// ---------------------------------------------------------------------------
__device__ __forceinline__ void cp16(uint32_t s, const void* g) {
    asm volatile("cp.async.cg.shared.global [%0], [%1], 16;\n" ::"r"(s), "l"(g) : "memory");
}

__device__ __forceinline__ void issue_tile(int tid, uint32_t sa, uint32_t sb,
                                           const __half* Ag, const __half* Bg,
                                           int k0) {
#pragma unroll
    for (int t = 0; t < 6; t++) {
        int ci = tid + t * 256;
        if (ci < 1024) {                       // A: 256 rows x 4 chunks
            int ar = ci >> 2, ac = (ci & 3) << 3;
            cp16(sa + (ar * A_ST + ac) * 2, Ag + (size_t)ar * K_DIM + k0 + ac);
        } else {                               // B: 32 rows x 16 chunks
            int cj = ci - 1024;
            int br = cj >> 4, bc = (cj & 15) << 3;
            cp16(sb + (br * B_ST + bc) * 2, Bg + (size_t)(k0 + br) * N_DIM + bc);
        }
    }
    asm volatile("cp.async.commit_group;\n" ::: "memory");
}

__global__ void __launch_bounds__(256, 1)
gemm_kernel(const float* __restrict__ bias, float* __restrict__ C) {
    extern __shared__ __align__(16) __half smem[];

    const int tid = threadIdx.x;
    const int lane = tid & 31;
    const int warp = tid >> 5;
    const int wm = warp >> 1;   // 0..3 (64-row slice)
    const int wn = warp & 1;    // 0..1 (64-col slice)
    const int bn = blockIdx.x;  // fastest: CTAs in a wave share the A slice
    const int bm = blockIdx.y;

    const __half* Ag = g_X + (size_t)bm * BM * K_DIM;
    const __half* Bg = g_W + (size_t)bn * BN;

    uint32_t sA[NSTAGE], sB[NSTAGE];
#pragma unroll
    for (int s = 0; s < NSTAGE; s++) {
        sA[s] = (uint32_t)__cvta_generic_to_shared(smem + s * STAGE_H);
        sB[s] = sA[s] + A_TILE_H * 2;
    }

    float acc[4][8][4];
#pragma unroll
    for (int i = 0; i < 4; i++)
#pragma unroll
        for (int j = 0; j < 8; j++)
#pragma unroll
            for (int k = 0; k < 4; k++) acc[i][j][k] = 0.0f;

    const int NKI = K_DIM / BK;  // 128
    issue_tile(tid, sA[0], sB[0], Ag, Bg, 0);
    issue_tile(tid, sA[1], sB[1], Ag, Bg, BK);

    for (int kt = 0; kt < NKI; kt++) {
        asm volatile("cp.async.wait_group 1;\n" ::: "memory");
        __syncthreads();
        int cur = kt % NSTAGE;
        if (kt + 2 < NKI)
            issue_tile(tid, sA[(kt + 2) % NSTAGE], sB[(kt + 2) % NSTAGE], Ag, Bg,
                       (kt + 2) * BK);

#pragma unroll
        for (int ks = 0; ks < 2; ks++) {
            uint32_t af[4][4];
#pragma unroll
            for (int mi = 0; mi < 4; mi++) {
                int m = wm * 64 + mi * 16 + (lane & 15);
                int kc = ks * 16 + ((lane >> 4) << 3);
                uint32_t addr = sA[cur] + (m * A_ST + kc) * 2;
                asm volatile(
                    "ldmatrix.sync.aligned.m8n8.x4.shared.b16 {%0,%1,%2,%3}, [%4];\n"
                    : "=r"(af[mi][0]), "=r"(af[mi][1]), "=r"(af[mi][2]), "=r"(af[mi][3])
                    : "r"(addr));
            }
            uint32_t bf[4][4];
#pragma unroll
            for (int nj = 0; nj < 4; nj++) {
                int kr = ks * 16 + (lane & 15);
                int n = wn * 64 + nj * 16 + ((lane >> 4) << 3);
                uint32_t addr = sB[cur] + (kr * B_ST + n) * 2;
                asm volatile(
                    "ldmatrix.sync.aligned.m8n8.x4.trans.shared.b16 {%0,%1,%2,%3}, [%4];\n"
                    : "=r"(bf[nj][0]), "=r"(bf[nj][1]), "=r"(bf[nj][2]), "=r"(bf[nj][3])
                    : "r"(addr));
            }
#pragma unroll
            for (int mi = 0; mi < 4; mi++)
#pragma unroll
                for (int ni = 0; ni < 8; ni++) {
                    uint32_t b0 = bf[ni >> 1][(ni & 1) * 2];
                    uint32_t b1 = bf[ni >> 1][(ni & 1) * 2 + 1];
                    asm volatile(
                        "mma.sync.aligned.m16n8k16.row.col.f32.f16.f16.f32 "
                        "{%0,%1,%2,%3}, {%4,%5,%6,%7}, {%8,%9}, {%0,%1,%2,%3};\n"
                        : "+f"(acc[mi][ni][0]), "+f"(acc[mi][ni][1]),
                          "+f"(acc[mi][ni][2]), "+f"(acc[mi][ni][3])
                        : "r"(af[mi][0]), "r"(af[mi][1]), "r"(af[mi][2]), "r"(af[mi][3]),
                          "r"(b0), "r"(b1));
                }
        }
    }

    // Epilogue: fp16(acc) + fp16(bias) in fp16 (reference semantics), widen to fp32.
#pragma unroll
    for (int mi = 0; mi < 4; mi++) {
        int r = bm * BM + wm * 64 + mi * 16 + (lane >> 2);
#pragma unroll
        for (int ni = 0; ni < 8; ni++) {
            int col = bn * BN + wn * 64 + ni * 8 + (lane & 3) * 2;
            __half b0 = __float2half_rn(bias[col]);
            __half b1 = __float2half_rn(bias[col + 1]);
            float2 v0, v1;
            v0.x = __half2float(__hadd(__float2half_rn(acc[mi][ni][0]), b0));
            v0.y = __half2float(__hadd(__float2half_rn(acc[mi][ni][1]), b1));
            v1.x = __half2float(__hadd(__float2half_rn(acc[mi][ni][2]), b0));
            v1.y = __half2float(__hadd(__float2half_rn(acc[mi][ni][3]), b1));
            *reinterpret_cast<float2*>(C + (size_t)r * N_DIM + col) = v0;
            *reinterpret_cast<float2*>(C + (size_t)(r + 8) * N_DIM + col) = v1;
        }
    }
}

extern "C" void kernel_launch(void* const* d_in, const int* in_sizes, int n_in,
                              void* d_out, int out_size) {
    // Resolve inputs by element count (ordering-proof):
    const float* x = nullptr;
    const int* qw = nullptr;
    const int* qz = nullptr;
    const float* sc = nullptr;
    const float* bias = nullptr;
    size_t x_elems = 0;
    for (int i = 0; i < n_in; i++) {
        int sz = in_sizes[i];
        if (sz == QROWS * N_DIM) qw = (const int*)d_in[i];
        else if (sz == 32 * (N_DIM / 8)) qz = (const int*)d_in[i];
        else if (sz == 32 * N_DIM) sc = (const float*)d_in[i];
        else if (sz == N_DIM) bias = (const float*)d_in[i];
        else if (sz == M_DIM * K_DIM) { x = (const float*)d_in[i]; x_elems = (size_t)sz; }
    }
    float* out = (float*)d_out;

    convert_x_kernel<<<(unsigned)((x_elems / 4 + 255) / 256), 256>>>(x, x_elems);

    dim3 dq_grid((N_DIM + 255) / 256, QROWS);
    dequant_kernel<<<dq_grid, 256>>>(qw, qz, sc);

    cudaFuncSetAttribute(gemm_kernel, cudaFuncAttributeMaxDynamicSharedMemorySize,
                         SMEM_BYTES);
    dim3 g_grid(N_DIM / BN, M_DIM / BM);  // (86, 16)
    gemm_kernel<<<g_grid, 256, SMEM_BYTES>>>(bias, out);
}

// round 9
// speedup vs baseline: 1.2516x; 1.2516x over previous
#include <cuda_runtime.h>
#include <cuda_fp16.h>
#include <cstdint>
#include <cstddef>

#define K_DIM 4096
#define N_DIM 11008
#define M_DIM 4096
#define QROWS (K_DIM / 8)

#define BM 128
#define BN 128
#define BK 32
#define A_ST (BK + 8)            // 40 halves = 80B stride
#define B_ST (BN + 8)            // 136 halves = 272B stride
#define NSTAGE 4
#define A_TILE_H (BM * A_ST)     // 5120 halves
#define B_TILE_H (BK * B_ST)     // 4352 halves
#define STAGE_H (A_TILE_H + B_TILE_H)      // 9472 halves = 18944 B
#define SMEM_BYTES (NSTAGE * STAGE_H * 2)  // 75776 B

// Scratch (device-code references only; host-side symbol addresses are the
// host shadow and GB300 ATS silently reads them as zeros).
__device__ __half g_W[(size_t)K_DIM * N_DIM];    // dequantized W [K, N]
__device__ __half g_X[(size_t)M_DIM * K_DIM];    // x as fp16 [M, K]

// ---------------------------------------------------------------------------
// Kernel 0: x fp32 -> fp16
// ---------------------------------------------------------------------------
__global__ void convert_x_kernel(const float* __restrict__ x, size_t n) {
    size_t i = ((size_t)blockIdx.x * blockDim.x + threadIdx.x) * 4;
    if (i >= n) return;
    float4 v = *reinterpret_cast<const float4*>(x + i);
    *reinterpret_cast<__half2*>(&g_X[i]) = __floats2half2_rn(v.x, v.y);
    *reinterpret_cast<__half2*>(&g_X[i + 2]) = __floats2half2_rn(v.z, v.w);
}

// ---------------------------------------------------------------------------
// Kernel 1: unpack int4 weights -> fp16 W[K, N]
// ---------------------------------------------------------------------------
__global__ void dequant_kernel(const int* __restrict__ qw,
                               const int* __restrict__ qz,
                               const float* __restrict__ sc) {
    int c = blockIdx.x * blockDim.x + threadIdx.x;
    if (c >= N_DIM) return;
    int kk = blockIdx.y;
    int packed = qw[kk * N_DIM + c];
    int g = kk >> 4;
    int z = (qz[g * (N_DIM / 8) + (c >> 3)] >> ((c & 7) * 4)) & 15;
    float s = sc[g * N_DIM + c];
    size_t base = (size_t)kk * 8 * N_DIM + c;
#pragma unroll
    for (int i = 0; i < 8; i++) {
        int q = (packed >> (i * 4)) & 15;
        g_W[base + (size_t)i * N_DIM] = __float2half((float)(q - z) * s);
    }
}

// ---------------------------------------------------------------------------
// Kernel 2: fp16 GEMM, 128x128x32 tile, 8 warps (2x4), 4-stage cp.async
// pipeline (wait_group 2) + register double-buffered fragments.
// ---------------------------------------------------------------------------
__device__ __forceinline__ void cp16(uint32_t s, const void* g) {
    asm volatile("cp.async.cg.shared.global [%0], [%1], 16;\n" ::"r"(s), "l"(g) : "memory");
}

__device__ __forceinline__ void issue_tile(int tid, uint32_t sa, uint32_t sb,
                                           const __half* Ag, const __half* Bg,
                                           int k0) {
#pragma unroll
    for (int t = 0; t < 2; t++) {
        int ci = tid + t * 256;
        int ar = ci >> 2, ac = (ci & 3) << 3;
        cp16(sa + (ar * A_ST + ac) * 2, Ag + (size_t)ar * K_DIM + k0 + ac);
        int br = ci >> 4, bc = (ci & 15) << 3;
        cp16(sb + (br * B_ST + bc) * 2, Bg + (size_t)(k0 + br) * N_DIM + bc);
    }
    asm volatile("cp.async.commit_group;\n" ::: "memory");
}

__device__ __forceinline__ void load_frags(uint32_t sa, uint32_t sb, int wm, int wn,
                                           int lane, int ks, uint32_t af[4][4],
                                           uint32_t bf[2][4]) {
#pragma unroll
    for (int mi = 0; mi < 4; mi++) {
        int m = wm * 64 + mi * 16 + (lane & 15);
        int kc = ks * 16 + ((lane >> 4) << 3);
        uint32_t addr = sa + (m * A_ST + kc) * 2;
        asm volatile("ldmatrix.sync.aligned.m8n8.x4.shared.b16 {%0,%1,%2,%3}, [%4];\n"
                     : "=r"(af[mi][0]), "=r"(af[mi][1]), "=r"(af[mi][2]), "=r"(af[mi][3])
                     : "r"(addr));
    }
#pragma unroll
    for (int nj = 0; nj < 2; nj++) {
        int kr = ks * 16 + (lane & 15);
        int n = wn * 32 + nj * 16 + ((lane >> 4) << 3);
        uint32_t addr = sb + (kr * B_ST + n) * 2;
        asm volatile("ldmatrix.sync.aligned.m8n8.x4.trans.shared.b16 {%0,%1,%2,%3}, [%4];\n"
                     : "=r"(bf[nj][0]), "=r"(bf[nj][1]), "=r"(bf[nj][2]), "=r"(bf[nj][3])
                     : "r"(addr));
    }
}

__device__ __forceinline__ void do_mmas(const uint32_t af[4][4], const uint32_t bf[2][4],
                                        float acc[4][4][4]) {
#pragma unroll
    for (int mi = 0; mi < 4; mi++)
#pragma unroll
        for (int ni = 0; ni < 4; ni++) {
            uint32_t b0 = bf[ni >> 1][(ni & 1) * 2];
            uint32_t b1 = bf[ni >> 1][(ni & 1) * 2 + 1];
            asm volatile(
                "mma.sync.aligned.m16n8k16.row.col.f32.f16.f16.f32 "
                "{%0,%1,%2,%3}, {%4,%5,%6,%7}, {%8,%9}, {%0,%1,%2,%3};\n"
                : "+f"(acc[mi][ni][0]), "+f"(acc[mi][ni][1]), "+f"(acc[mi][ni][2]),
                  "+f"(acc[mi][ni][3])
                : "r"(af[mi][0]), "r"(af[mi][1]), "r"(af[mi][2]), "r"(af[mi][3]),
                  "r"(b0), "r"(b1));
        }
}

__global__ void __launch_bounds__(256, 2)
gemm_kernel(const float* __restrict__ bias, float* __restrict__ C) {
    extern __shared__ __align__(16) __half smem[];

    const int tid = threadIdx.x;
    const int lane = tid & 31;
    const int warp = tid >> 5;
    const int wm = warp >> 2;   // 0..1
    const int wn = warp & 3;    // 0..3
    const int bn = blockIdx.x;
    const int bm = blockIdx.y;

    const __half* Ag = g_X + (size_t)bm * BM * K_DIM;
    const __half* Bg = g_W + (size_t)bn * BN;

    uint32_t sA[NSTAGE], sB[NSTAGE];
#pragma unroll
    for (int s = 0; s < NSTAGE; s++) {
        sA[s] = (uint32_t)__cvta_generic_to_shared(smem + s * STAGE_H);
        sB[s] = sA[s] + A_TILE_H * 2;
    }

    float acc[4][4][4];
#pragma unroll
    for (int i = 0; i < 4; i++)
#pragma unroll
        for (int j = 0; j < 4; j++)
#pragma unroll
            for (int k = 0; k < 4; k++) acc[i][j][k] = 0.0f;

    const int NKI = K_DIM / BK;  // 128
    issue_tile(tid, sA[0], sB[0], Ag, Bg, 0);
    issue_tile(tid, sA[1], sB[1], Ag, Bg, BK);
    issue_tile(tid, sA[2], sB[2], Ag, Bg, 2 * BK);

    uint32_t af[2][4][4], bf[2][2][4];

    for (int kt = 0; kt < NKI; kt++) {
        asm volatile("cp.async.wait_group 2;\n" ::: "memory");
        __syncthreads();
        int cur = kt % NSTAGE;

        // Fragments for ks=0.
        load_frags(sA[cur], sB[cur], wm, wn, lane, 0, af[0], bf[0]);

        if (kt + 3 < NKI)
            issue_tile(tid, sA[(kt + 3) % NSTAGE], sB[(kt + 3) % NSTAGE], Ag, Bg,
                       (kt + 3) * BK);

        // Prefetch ks=1 fragments; MMAs on buffer 0 overlap with these LDSMs.
        load_frags(sA[cur], sB[cur], wm, wn, lane, 1, af[1], bf[1]);
        do_mmas(af[0], bf[0], acc);
        do_mmas(af[1], bf[1], acc);
    }

    // Epilogue: fp16(acc) + fp16(bias) in fp16 (reference semantics), widen to fp32.
#pragma unroll
    for (int mi = 0; mi < 4; mi++) {
        int r = bm * BM + wm * 64 + mi * 16 + (lane >> 2);
#pragma unroll
        for (int ni = 0; ni < 4; ni++) {
            int col = bn * BN + wn * 32 + ni * 8 + (lane & 3) * 2;
            __half b0 = __float2half_rn(bias[col]);
            __half b1 = __float2half_rn(bias[col + 1]);
            float2 v0, v1;
            v0.x = __half2float(__hadd(__float2half_rn(acc[mi][ni][0]), b0));
            v0.y = __half2float(__hadd(__float2half_rn(acc[mi][ni][1]), b1));
            v1.x = __half2float(__hadd(__float2half_rn(acc[mi][ni][2]), b0));
            v1.y = __half2float(__hadd(__float2half_rn(acc[mi][ni][3]), b1));
            *reinterpret_cast<float2*>(C + (size_t)r * N_DIM + col) = v0;
            *reinterpret_cast<float2*>(C + (size_t)(r + 8) * N_DIM + col) = v1;
        }
    }
}

extern "C" void kernel_launch(void* const* d_in, const int* in_sizes, int n_in,
                              void* d_out, int out_size) {
    const float* x = nullptr;
    const int* qw = nullptr;
    const int* qz = nullptr;
    const float* sc = nullptr;
    const float* bias = nullptr;
    size_t x_elems = 0;
    for (int i = 0; i < n_in; i++) {
        int sz = in_sizes[i];
        if (sz == QROWS * N_DIM) qw = (const int*)d_in[i];
        else if (sz == 32 * (N_DIM / 8)) qz = (const int*)d_in[i];
        else if (sz == 32 * N_DIM) sc = (const float*)d_in[i];
        else if (sz == N_DIM) bias = (const float*)d_in[i];
        else if (sz == M_DIM * K_DIM) { x = (const float*)d_in[i]; x_elems = (size_t)sz; }
    }
    float* out = (float*)d_out;

    convert_x_kernel<<<(unsigned)((x_elems / 4 + 255) / 256), 256>>>(x, x_elems);

    dim3 dq_grid((N_DIM + 255) / 256, QROWS);
    dequant_kernel<<<dq_grid, 256>>>(qw, qz, sc);

    cudaFuncSetAttribute(gemm_kernel, cudaFuncAttributeMaxDynamicSharedMemorySize,
                         SMEM_BYTES);
    dim3 g_grid(N_DIM / BN, M_DIM / BM);  // (86, 32)
    gemm_kernel<<<g_grid, 256, SMEM_BYTES>>>(bias, out);
}